// round 13
// baseline (speedup 1.0000x reference)
#include <cuda_runtime.h>
#include <cstdint>

// DIoU loss, HBM-bound streaming reduction (144 MB read, scalar out).
// R13: R12 work-stealing design with UNROLL=8 (tile=2048, 24 front-batched
// LDGs/thread). Work stealing makes register-driven occupancy loss benign
// (late CTAs steal less), so we can finally afford the deeper load batch
// that static scheduling couldn't (R3). Atomics+syncs also halve.

#define EPS 1e-7f
#define UNROLL 8
#define THREADS 256
#define TILE (THREADS * UNROLL)
#define MAX_BLOCKS 4096

__device__ float g_partials[MAX_BLOCKS];
__device__ unsigned int g_ticket = 0;   // finalize election
__device__ unsigned int g_work = 0;     // dynamic tile ticket

__device__ __forceinline__ float diou_loss(float4 a, float4 b) {
    float area1 = (a.z - a.x) * (a.w - a.y);
    float area2 = (b.z - b.x) * (b.w - b.y);

    float ltx = fmaxf(a.x, b.x);
    float lty = fmaxf(a.y, b.y);
    float rbx = fminf(a.z, b.z);
    float rby = fminf(a.w, b.w);
    float iw = fmaxf(rbx - ltx, 0.0f);
    float ih = fmaxf(rby - lty, 0.0f);
    float inter = iw * ih;
    float uni = area1 + area2 - inter;

    float cltx = fminf(a.x, b.x);
    float clty = fminf(a.y, b.y);
    float crbx = fmaxf(a.z, b.z);
    float crby = fmaxf(a.w, b.w);
    float wc = crbx - cltx;
    float hc = crby - clty;
    float area_c = wc * hc;

    float iou = __fdividef(inter, uni);
    float giou = iou - __fdividef(area_c - uni, area_c);

    float dcx = (a.x + a.z) * 0.5f - (b.x + b.z) * 0.5f;
    float dcy = (a.y + a.w) * 0.5f - (b.y + b.w) * 0.5f;
    float d2 = dcx * dcx + dcy * dcy;
    float diag2 = wc * wc + hc * hc;
    float diou = giou - __fdividef(d2, diag2 + EPS);

    return 1.0f - diou;
}

__device__ __forceinline__ void prefetch_l2(const void* p) {
    asm volatile("prefetch.global.L2 [%0];" :: "l"(p));
}

__global__ void __launch_bounds__(THREADS)
diou_kernel(const float4* __restrict__ boxes1,
            const float4* __restrict__ boxes2,
            const int* __restrict__ mask,
            const int* __restrict__ num_boxes,
            float* __restrict__ out,
            int N, int numTiles) {
    __shared__ int s_next;
    __shared__ float warp_sums[THREADS / 32];
    __shared__ bool is_last;

    int tid = threadIdx.x;
    int lane = tid & 31;
    int wid = tid >> 5;

    float acc = 0.0f;

    // Grab first tile.
    if (tid == 0) s_next = (int)atomicAdd(&g_work, 1u);
    __syncthreads();
    int t = s_next;

    while (t < numTiles) {
        // Acquire next ticket early (overlaps with this tile's loads).
        if (tid == 0) s_next = (int)atomicAdd(&g_work, 1u);

        int base = t * TILE + tid;
        // Front-batched unconditional loads: 24 LDGs in flight.
        float4 a[UNROLL], b[UNROLL];
        int m[UNROLL];
        #pragma unroll
        for (int j = 0; j < UNROLL; j++) {
            int i = base + j * THREADS;
            a[j] = __ldcs(&boxes1[i]);
            b[j] = __ldcs(&boxes2[i]);
            m[j] = __ldcs(&mask[i]);
        }

        __syncthreads();  // s_next visible to all threads
        int tn = s_next;

        // Prefetch next tile into L2 while this tile's loads are in flight.
        if (tn < numTiles) {
            int pb = tn * TILE + tid;
            #pragma unroll
            for (int j = 0; j < UNROLL; j++) {
                prefetch_l2(&boxes1[pb + j * THREADS]);
                prefetch_l2(&boxes2[pb + j * THREADS]);
                prefetch_l2(&mask[pb + j * THREADS]);
            }
        }

        #pragma unroll
        for (int j = 0; j < UNROLL; j++)
            acc += diou_loss(a[j], b[j]) * (float)(m[j] != 0);

        t = tn;
    }

    // Ragged tail beyond full tiles (none for N = 4096*1024; safety).
    if (blockIdx.x == 0) {
        for (int i = numTiles * TILE + tid; i < N; i += THREADS) {
            float4 a = __ldcs(&boxes1[i]);
            float4 b = __ldcs(&boxes2[i]);
            int m = __ldcs(&mask[i]);
            acc += diou_loss(a, b) * (float)(m != 0);
        }
    }

    // Block reduce.
    #pragma unroll
    for (int off = 16; off > 0; off >>= 1)
        acc += __shfl_down_sync(0xFFFFFFFFu, acc, off);

    if (lane == 0) warp_sums[wid] = acc;
    __syncthreads();

    if (wid == 0) {
        float v = (lane < THREADS / 32) ? warp_sums[lane] : 0.0f;
        #pragma unroll
        for (int off = 4; off > 0; off >>= 1)
            v += __shfl_down_sync(0xFFFFFFFFu, v, off);
        if (lane == 0) {
            g_partials[blockIdx.x] = v;
            __threadfence();
            unsigned int ticket = atomicAdd(&g_ticket, 1u);
            is_last = (ticket == gridDim.x - 1);
        }
    }
    __syncthreads();

    // Last block: reduce partials, write out, reset tickets for next replay.
    if (is_last) {
        float v = 0.0f;
        for (int i = threadIdx.x; i < gridDim.x; i += THREADS)
            v += g_partials[i];
        #pragma unroll
        for (int off = 16; off > 0; off >>= 1)
            v += __shfl_down_sync(0xFFFFFFFFu, v, off);
        if (lane == 0) warp_sums[wid] = v;
        __syncthreads();
        if (wid == 0) {
            float s = (lane < THREADS / 32) ? warp_sums[lane] : 0.0f;
            #pragma unroll
            for (int off = 4; off > 0; off >>= 1)
                s += __shfl_down_sync(0xFFFFFFFFu, s, off);
            if (lane == 0) {
                g_ticket = 0;
                g_work = 0;
                out[0] = s * (1.0f / (float)num_boxes[0]);
            }
        }
    }
}

extern "C" void kernel_launch(void* const* d_in, const int* in_sizes, int n_in,
                              void* d_out, int out_size) {
    const float4* boxes1 = (const float4*)d_in[0];
    const float4* boxes2 = (const float4*)d_in[1];
    const int* mask = (const int*)d_in[2];
    const int* num_boxes = (const int*)d_in[3];
    float* out = (float*)d_out;

    int N = in_sizes[0] / 4;   // B*Q elements
    int numTiles = N / TILE;   // 2048 full tiles

    // 888 CTAs launched; residency-driven arrival skew is absorbed by
    // the dynamic ticket (late CTAs steal less).
    int blocks = 148 * 6;
    if (blocks > MAX_BLOCKS) blocks = MAX_BLOCKS;
    if (blocks < 1) blocks = 1;

    diou_kernel<<<blocks, THREADS>>>(boxes1, boxes2, mask, num_boxes, out,
                                     N, numTiles);
}

// round 14
// speedup vs baseline: 1.1664x; 1.1664x over previous
#include <cuda_runtime.h>
#include <cstdint>

// DIoU loss, HBM-bound streaming reduction (144 MB read, scalar out).
// R14: R12 work-stealing design (UNROLL=4, front-batched 12 LDGs + L2
// prefetch of the stolen next tile, single-launch finalize) with grid
// sized to the ACTUAL residency at 55 regs: 4 CTAs/SM -> 592 CTAs, all
// in wave 1. R12's 888-CTA launch left 296 second-wave CTAs that stole
// nothing but delayed the finalize election by a full wave transition.

#define EPS 1e-7f
#define UNROLL 4
#define THREADS 256
#define TILE (THREADS * UNROLL)
#define MAX_BLOCKS 4096

__device__ float g_partials[MAX_BLOCKS];
__device__ unsigned int g_ticket = 0;   // finalize election
__device__ unsigned int g_work = 0;     // dynamic tile ticket

__device__ __forceinline__ float diou_loss(float4 a, float4 b) {
    float area1 = (a.z - a.x) * (a.w - a.y);
    float area2 = (b.z - b.x) * (b.w - b.y);

    float ltx = fmaxf(a.x, b.x);
    float lty = fmaxf(a.y, b.y);
    float rbx = fminf(a.z, b.z);
    float rby = fminf(a.w, b.w);
    float iw = fmaxf(rbx - ltx, 0.0f);
    float ih = fmaxf(rby - lty, 0.0f);
    float inter = iw * ih;
    float uni = area1 + area2 - inter;

    float cltx = fminf(a.x, b.x);
    float clty = fminf(a.y, b.y);
    float crbx = fmaxf(a.z, b.z);
    float crby = fmaxf(a.w, b.w);
    float wc = crbx - cltx;
    float hc = crby - clty;
    float area_c = wc * hc;

    float iou = __fdividef(inter, uni);
    float giou = iou - __fdividef(area_c - uni, area_c);

    float dcx = (a.x + a.z) * 0.5f - (b.x + b.z) * 0.5f;
    float dcy = (a.y + a.w) * 0.5f - (b.y + b.w) * 0.5f;
    float d2 = dcx * dcx + dcy * dcy;
    float diag2 = wc * wc + hc * hc;
    float diou = giou - __fdividef(d2, diag2 + EPS);

    return 1.0f - diou;
}

__device__ __forceinline__ void prefetch_l2(const void* p) {
    asm volatile("prefetch.global.L2 [%0];" :: "l"(p));
}

__global__ void __launch_bounds__(THREADS)
diou_kernel(const float4* __restrict__ boxes1,
            const float4* __restrict__ boxes2,
            const int* __restrict__ mask,
            const int* __restrict__ num_boxes,
            float* __restrict__ out,
            int N, int numTiles) {
    __shared__ int s_next;
    __shared__ float warp_sums[THREADS / 32];
    __shared__ bool is_last;

    int tid = threadIdx.x;
    int lane = tid & 31;
    int wid = tid >> 5;

    float acc = 0.0f;

    // Grab first tile.
    if (tid == 0) s_next = (int)atomicAdd(&g_work, 1u);
    __syncthreads();
    int t = s_next;

    while (t < numTiles) {
        // Acquire next ticket early (overlaps with this tile's loads).
        if (tid == 0) s_next = (int)atomicAdd(&g_work, 1u);

        int base = t * TILE + tid;
        // Front-batched unconditional loads: 12 LDGs in flight.
        float4 a[UNROLL], b[UNROLL];
        int m[UNROLL];
        #pragma unroll
        for (int j = 0; j < UNROLL; j++) {
            int i = base + j * THREADS;
            a[j] = __ldcs(&boxes1[i]);
            b[j] = __ldcs(&boxes2[i]);
            m[j] = __ldcs(&mask[i]);
        }

        __syncthreads();  // s_next visible to all threads
        int tn = s_next;

        // Prefetch next tile into L2 while this tile's loads are in flight.
        if (tn < numTiles) {
            int pb = tn * TILE + tid;
            #pragma unroll
            for (int j = 0; j < UNROLL; j++) {
                prefetch_l2(&boxes1[pb + j * THREADS]);
                prefetch_l2(&boxes2[pb + j * THREADS]);
                prefetch_l2(&mask[pb + j * THREADS]);
            }
        }

        #pragma unroll
        for (int j = 0; j < UNROLL; j++)
            acc += diou_loss(a[j], b[j]) * (float)(m[j] != 0);

        t = tn;
    }

    // Ragged tail beyond full tiles (none for N = 4096*1024; safety).
    if (blockIdx.x == 0) {
        for (int i = numTiles * TILE + tid; i < N; i += THREADS) {
            float4 a = __ldcs(&boxes1[i]);
            float4 b = __ldcs(&boxes2[i]);
            int m = __ldcs(&mask[i]);
            acc += diou_loss(a, b) * (float)(m != 0);
        }
    }

    // Block reduce.
    #pragma unroll
    for (int off = 16; off > 0; off >>= 1)
        acc += __shfl_down_sync(0xFFFFFFFFu, acc, off);

    if (lane == 0) warp_sums[wid] = acc;
    __syncthreads();

    if (wid == 0) {
        float v = (lane < THREADS / 32) ? warp_sums[lane] : 0.0f;
        #pragma unroll
        for (int off = 4; off > 0; off >>= 1)
            v += __shfl_down_sync(0xFFFFFFFFu, v, off);
        if (lane == 0) {
            g_partials[blockIdx.x] = v;
            __threadfence();
            unsigned int ticket = atomicAdd(&g_ticket, 1u);
            is_last = (ticket == gridDim.x - 1);
        }
    }
    __syncthreads();

    // Last block: reduce partials, write out, reset tickets for next replay.
    if (is_last) {
        float v = 0.0f;
        for (int i = threadIdx.x; i < gridDim.x; i += THREADS)
            v += g_partials[i];
        #pragma unroll
        for (int off = 16; off > 0; off >>= 1)
            v += __shfl_down_sync(0xFFFFFFFFu, v, off);
        if (lane == 0) warp_sums[wid] = v;
        __syncthreads();
        if (wid == 0) {
            float s = (lane < THREADS / 32) ? warp_sums[lane] : 0.0f;
            #pragma unroll
            for (int off = 4; off > 0; off >>= 1)
                s += __shfl_down_sync(0xFFFFFFFFu, s, off);
            if (lane == 0) {
                g_ticket = 0;
                g_work = 0;
                out[0] = s * (1.0f / (float)num_boxes[0]);
            }
        }
    }
}

extern "C" void kernel_launch(void* const* d_in, const int* in_sizes, int n_in,
                              void* d_out, int out_size) {
    const float4* boxes1 = (const float4*)d_in[0];
    const float4* boxes2 = (const float4*)d_in[1];
    const int* mask = (const int*)d_in[2];
    const int* num_boxes = (const int*)d_in[3];
    float* out = (float*)d_out;

    int N = in_sizes[0] / 4;   // B*Q elements
    int numTiles = N / TILE;   // 4096 full tiles

    // 592 = 148 SMs * 4 CTAs (55 regs) -> every CTA resident in wave 1;
    // work stealing handles any per-SM skew.
    int blocks = 148 * 4;
    if (blocks > MAX_BLOCKS) blocks = MAX_BLOCKS;
    if (blocks < 1) blocks = 1;

    diou_kernel<<<blocks, THREADS>>>(boxes1, boxes2, mask, num_boxes, out,
                                     N, numTiles);
}